// round 7
// baseline (speedup 1.0000x reference)
#include <cuda_runtime.h>
#include <cuda_bf16.h>

#define BSZ 8
#define LEN 4096
#define DM  128   // d_model (M)
#define DS  128   // d_state (N)

#define TO 1024   // output tile (time) per CTA
#define TU 128    // input tile (time)
#define NT 128    // threads per CTA (conv)
#define RR 8      // output rows (l = t0 + tid + r*128) per thread

// -------- scratch (__device__ globals; no allocation allowed) --------
__device__ float g_xt[BSZ * DM * LEN];    // x transposed to (b, m, l)
__device__ float g_psum[DS * LEN];        // Psum[k, l]
__device__ float g_kern[DM * LEN];        // kernel[m, l]
__device__ float g_G[DM * DS];            // G = C @ B

using u64 = unsigned long long;
__device__ __forceinline__ void ffma2(u64 &d, u64 a, u64 b) {
    asm("fma.rn.f32x2 %0, %1, %2, %0;" : "+l"(d) : "l"(a), "l"(b));
}
__device__ __forceinline__ u64 pack2(float lo, float hi) {
    u64 r; asm("mov.b64 %0, {%1, %2};" : "=l"(r) : "f"(lo), "f"(hi)); return r;
}
__device__ __forceinline__ void unpack2(u64 v, float &lo, float &hi) {
    asm("mov.b64 {%0, %1}, %2;" : "=f"(lo), "=f"(hi) : "l"(v));
}

// -------- 1) transpose x (b,l,m) -> (b,m,l) --------
__global__ void transpose_kernel(const float* __restrict__ x) {
    __shared__ float tile[32][33];
    int b  = blockIdx.z;
    int l0 = blockIdx.x * 32;
    int m0 = blockIdx.y * 32;
    int tx = threadIdx.x, ty = threadIdx.y;
#pragma unroll
    for (int j = 0; j < 32; j += 8)
        tile[ty + j][tx] = x[(b * LEN + l0 + ty + j) * DM + m0 + tx];
    __syncthreads();
#pragma unroll
    for (int j = 0; j < 32; j += 8)
        g_xt[(b * DM + m0 + ty + j) * LEN + l0 + tx] = tile[tx][ty + j];
}

// -------- 2) Psum[k,l] = sum_{m'} exp(dt[m'] * Lam[k] * l) --------
__global__ void psum_kernel(const float* __restrict__ Lam,
                            const float* __restrict__ log_dt) {
    __shared__ float dt_s[DM];
    int k = blockIdx.x;
    int l = blockIdx.y * 128 + threadIdx.x;
    dt_s[threadIdx.x] = __expf(log_dt[threadIdx.x]);
    __syncthreads();
    float a = Lam[k] * (float)l;   // <= 0
    float s = 0.f;
#pragma unroll 8
    for (int mp = 0; mp < DM; ++mp)
        s += __expf(dt_s[mp] * a);
    g_psum[k * LEN + l] = s;
}

// -------- 3) G = C @ B --------
__global__ void gmat_kernel(const float* __restrict__ Bm,
                            const float* __restrict__ Cm) {
    __shared__ float c_s[DS];
    int m = blockIdx.x;
    int k = threadIdx.x;
    c_s[k] = Cm[m * DS + k];
    __syncthreads();
    float g = 0.f;
#pragma unroll 8
    for (int i = 0; i < DS; ++i)
        g = fmaf(c_s[i], Bm[i * DM + k], g);
    g_G[m * DS + k] = g;
}

// -------- 4) kernel[m,l] = sum_k G[m,k] * Psum[k,l] --------
// float4 psum loads for MLP; 8 m x 4 l per thread. grid (16, 8), block 128.
__global__ void __launch_bounds__(128) kern_kernel() {
    __shared__ float gs[8][DS];
    const int m0 = blockIdx.x * 8;
    const int l  = blockIdx.y * 512 + threadIdx.x * 4;
#pragma unroll
    for (int r = 0; r < 8; ++r)
        gs[r][threadIdx.x] = g_G[(m0 + r) * DS + threadIdx.x];
    __syncthreads();
    float4 a[8];
#pragma unroll
    for (int r = 0; r < 8; ++r) a[r] = make_float4(0.f, 0.f, 0.f, 0.f);
#pragma unroll 4
    for (int k = 0; k < DS; ++k) {
        float4 p = *(const float4*)(g_psum + k * LEN + l);
#pragma unroll
        for (int r = 0; r < 8; ++r) {
            float g = gs[r][k];
            a[r].x = fmaf(g, p.x, a[r].x);
            a[r].y = fmaf(g, p.y, a[r].y);
            a[r].z = fmaf(g, p.z, a[r].z);
            a[r].w = fmaf(g, p.w, a[r].w);
        }
    }
#pragma unroll
    for (int r = 0; r < 8; ++r)
        *(float4*)(g_kern + (m0 + r) * LEN + l) = a[r];
}

// -------- 5) causal conv + skip, tap-paired f32x2 FMA --------
// acc halves hold even-u / odd-u partial sums:
//   acc.lo += k[l-u]*x[u],  acc.hi += k[l-u-1]*x[u+1]
// kv2 = adjacent entries of REVERSED kernel (kr[i] = krow[j_hi - i]);
// two 4B-staggered copies resolve per-thread pair parity.
// xv2 = (x[u], x[u+1]) aligned broadcast LDS.64, shared across all rows.
__global__ void __launch_bounds__(NT) conv_kernel(const float* __restrict__ Dv,
                                                  float* __restrict__ out) {
    __shared__ __align__(16) float krs0[TO + TU];   // kr[i]
    __shared__ __align__(16) float krs1[TO + TU];   // kr[i+1]
    __shared__ __align__(16) float xs[BSZ][TU];

    const int bid = blockIdx.x;
    const int tt  = 3 - (bid & 3);        // interleave tile weights across bids
    const int m   = bid >> 2;
    const int t0  = tt * TO;
    const int tid = threadIdx.x;

    u64 acc[RR][BSZ];
#pragma unroll
    for (int r = 0; r < RR; ++r)
#pragma unroll
        for (int b = 0; b < BSZ; ++b) acc[r][b] = 0ull;

    const float* krow = g_kern + m * LEN;
    const int n_u = (t0 + TO) / TU;
    const int sel = (tid & 1) ^ 1;                      // 1 if tid even
    const float2* kp = (const float2*)(sel ? krs1 : krs0);
    // per-row base half-index (du = 0); q0_r - sel is even, >= 0
    int qh[RR];
#pragma unroll
    for (int r = 0; r < RR; ++r)
        qh[r] = (TO - 1 - tid - r * 128 - sel) >> 1;

    for (int ut = 0; ut < n_u; ++ut) {
        const int u0 = ut * TU;
        __syncthreads();
        const int j_hi = t0 + TO - 1 - u0;
#pragma unroll
        for (int i = tid; i < TO + TU; i += NT) {       // 9 iters
            int j = j_hi - i;
            krs0[i] = (j >= 0) ? krow[j] : 0.f;
            krs1[i] = (j >= 1) ? krow[j - 1] : 0.f;
        }
        {
            const float* xp = g_xt + m * LEN + u0 + tid;
#pragma unroll
            for (int b = 0; b < BSZ; ++b)
                xs[b][tid] = xp[b * DM * LEN];
        }
        __syncthreads();

#pragma unroll 2
        for (int dh = 0; dh < TU / 2; ++dh) {
            u64 xv[BSZ];
#pragma unroll
            for (int b = 0; b < BSZ; ++b) {
                float2 v = ((const float2*)xs[b])[dh];
                xv[b] = pack2(v.x, v.y);
            }
#pragma unroll
            for (int r = 0; r < RR; ++r) {
                float2 kv = kp[qh[r] + dh];
                u64 k2 = pack2(kv.x, kv.y);
#pragma unroll
                for (int b = 0; b < BSZ; ++b)
                    ffma2(acc[r][b], k2, xv[b]);
            }
        }
    }

    // epilogue: fold halves, add skip, store to (b, l, m)
    const float dv = Dv[m];
#pragma unroll
    for (int r = 0; r < RR; ++r) {
        int l = t0 + tid + r * 128;
#pragma unroll
        for (int b = 0; b < BSZ; ++b) {
            float lo, hi;
            unpack2(acc[r][b], lo, hi);
            float xval = g_xt[(b * DM + m) * LEN + l];
            out[(b * LEN + l) * DM + m] = fmaf(dv, xval, lo + hi);
        }
    }
}

extern "C" void kernel_launch(void* const* d_in, const int* in_sizes, int n_in,
                              void* d_out, int out_size) {
    const float* x      = (const float*)d_in[0];  // (8, 4096, 128)
    const float* Lam    = (const float*)d_in[1];  // (128,)
    const float* Bm     = (const float*)d_in[2];  // (128, 128)
    const float* Cm     = (const float*)d_in[3];  // (128, 128)
    const float* Dv     = (const float*)d_in[4];  // (128,)
    const float* log_dt = (const float*)d_in[5];  // (128,)
    float* out = (float*)d_out;

    transpose_kernel<<<dim3(LEN / 32, DM / 32, BSZ), dim3(32, 8)>>>(x);
    psum_kernel<<<dim3(DS, LEN / 128), 128>>>(Lam, log_dt);
    gmat_kernel<<<DM, DS>>>(Bm, Cm);
    kern_kernel<<<dim3(DM / 8, LEN / 512), 128>>>();
    conv_kernel<<<(LEN / TO) * DM, NT>>>(Dv, out);
}